// round 14
// baseline (speedup 1.0000x reference)
#include <cuda_runtime.h>
#include <cuda_bf16.h>
#include <cstdint>
#include <math.h>

#define NB 32
#define DIM 4096
#define NKV 8
#define NREP 4
#define HD 128
#define MAXSEQ 2048
#define NCHUNK 4
#define CHUNK 512
#define NTILE 16
#define QKV_SPLIT 8
#define O_SPLIT 8
#define TSS 132   // tile row stride (floats)

// ------------------------- device scratch (no allocs allowed) ---------------
__device__ float g_q[NB * DIM];                          // rope'd Q
__device__ float g_k[NB * NKV * HD];                     // rope'd new K row
__device__ float g_v[NB * NKV * HD];                     // new V row
__device__ float g_attn[NB * DIM];                       // attention output
__device__ float g_part[QKV_SPLIT * NB * 6144];          // split-K partials
__device__ float g_pout[NB * NKV * NCHUNK * 4 * NREP * HD];  // per-warp partials
__device__ float g_ml[NB * NKV * NREP * NCHUNK * 2];     // (m, l) per chunk

// ------------------------- bf16x3 MMA projection GEMM -----------------------
#define MMA_B16(acc, A0, A1, A2, A3, B0, B1)                                   \
    asm volatile(                                                              \
        "mma.sync.aligned.m16n8k16.row.col.f32.bf16.bf16.f32 "                 \
        "{%0,%1,%2,%3}, {%4,%5,%6,%7}, {%8,%9}, {%0,%1,%2,%3};"                \
        : "+f"(acc[0]), "+f"(acc[1]), "+f"(acc[2]), "+f"(acc[3])               \
        : "r"(A0), "r"(A1), "r"(A2), "r"(A3), "r"(B0), "r"(B1))

// packed split: one F2FP.PACK for hi pair, one for lo pair
__device__ __forceinline__ void bf16_split2(float2 v, unsigned& uh, unsigned& ul)
{
    __nv_bfloat162 hb = __floats2bfloat162_rn(v.x, v.y);
    float2 hf = __bfloat1622float2(hb);
    __nv_bfloat162 lb = __floats2bfloat162_rn(v.x - hf.x, v.y - hf.y);
    uh = *reinterpret_cast<unsigned*>(&hb);
    ul = *reinterpret_cast<unsigned*>(&lb);
}

__global__ __launch_bounds__(128) void proj_mma(
    const float* __restrict__ A,   // NB x 4096 (nullptr -> g_attn)
    const float* __restrict__ W0,
    const float* __restrict__ W1,
    const float* __restrict__ W2,
    int njb, int r1, int r2, int klen, int totalj)
{
    __shared__ unsigned sB[16 * 4 * 144];   // 36 KB
    __shared__ unsigned sAh[2 * 4 * 132];   // 4.2 KB
    __shared__ unsigned sAl[2 * 4 * 132];   // 4.2 KB

    const float* Ap = A ? A : g_attn;

    int jb    = blockIdx.x % njb;
    int split = blockIdx.x / njb;
    int j0    = jb * 128;

    const float* W;
    int jw;
    if (j0 < r1)      { W = W0; jw = j0; }
    else if (j0 < r2) { W = W1; jw = j0 - r1; }
    else              { W = W2; jw = j0 - r2; }

    int tid = threadIdx.x;
    int w   = tid >> 5, l = tid & 31;

    float acc[2][4][4];
#pragma unroll
    for (int i = 0; i < 2; i++)
#pragma unroll
        for (int j = 0; j < 4; j++)
#pragma unroll
            for (int c = 0; c < 4; c++) acc[i][j][c] = 0.f;

    int k0 = split * klen;
    int ksw   = l >> 3;
    int prw   = (l >> 2) & 1;
    int lq    = l & 3;

    for (int kc = k0; kc < k0 + klen; kc += 64) {
        __syncthreads();
#pragma unroll 4
        for (int rr = 0; rr < 32; rr++) {
            int n = w * 32 + rr;
            float2 v = *(const float2*)(W + (size_t)(jw + n) * 4096 + kc + 2 * l);
            unsigned uh, ul;
            bf16_split2(v, uh, ul);
            int nt = n >> 3;
            int lanep = ((n & 7) << 2) + lq;
            *(uint2*)&sB[((nt * 4 + ksw) * 144) + lanep * 4 + prw * 2] =
                make_uint2(uh, ul);
        }
#pragma unroll
        for (int rr = 0; rr < 8; rr++) {
            int m = w * 8 + rr;
            float2 v = *(const float2*)(Ap + (size_t)m * 4096 + kc + 2 * l);
            unsigned uh, ul;
            bf16_split2(v, uh, ul);
            int mt = m >> 4;
            int lanep = ((m & 7) << 2) + lq;
            int anum  = ((m >> 3) & 1) | (prw << 1);
            int idx = (mt * 4 + ksw) * 132 + lanep * 4 + anum;
            sAh[idx] = uh;
            sAl[idx] = ul;
        }
        __syncthreads();

#pragma unroll
        for (int ks = 0; ks < 4; ks++) {
            uint4 ah0 = *(const uint4*)&sAh[(ks) * 132 + l * 4];
            uint4 al0 = *(const uint4*)&sAl[(ks) * 132 + l * 4];
            uint4 ah1 = *(const uint4*)&sAh[(4 + ks) * 132 + l * 4];
            uint4 al1 = *(const uint4*)&sAl[(4 + ks) * 132 + l * 4];
#pragma unroll
            for (int ntl = 0; ntl < 4; ntl++) {
                uint4 bb = *(const uint4*)&sB[((w * 4 + ntl) * 4 + ks) * 144 + l * 4];
                MMA_B16(acc[0][ntl], ah0.x, ah0.y, ah0.z, ah0.w, bb.x, bb.z);
                MMA_B16(acc[1][ntl], ah1.x, ah1.y, ah1.z, ah1.w, bb.x, bb.z);
                MMA_B16(acc[0][ntl], al0.x, al0.y, al0.z, al0.w, bb.x, bb.z);
                MMA_B16(acc[1][ntl], al1.x, al1.y, al1.z, al1.w, bb.x, bb.z);
                MMA_B16(acc[0][ntl], ah0.x, ah0.y, ah0.z, ah0.w, bb.y, bb.w);
                MMA_B16(acc[1][ntl], ah1.x, ah1.y, ah1.z, ah1.w, bb.y, bb.w);
            }
        }
    }

    size_t pbase = (size_t)split * NB * totalj;
#pragma unroll
    for (int mt = 0; mt < 2; mt++)
#pragma unroll
        for (int ntl = 0; ntl < 4; ntl++) {
            int m = mt * 16 + (l >> 2);
            int j = j0 + ((w * 4 + ntl) << 3) + (lq << 1);
            *(float2*)&g_part[pbase + (size_t)m * totalj + j] =
                make_float2(acc[mt][ntl][0], acc[mt][ntl][1]);
            *(float2*)&g_part[pbase + (size_t)(m + 8) * totalj + j] =
                make_float2(acc[mt][ntl][2], acc[mt][ntl][3]);
        }
}

// ------------------------- split-K reduce + RoPE (float4) -------------------
__global__ void qkv_finish(const float* __restrict__ fc, const float* __restrict__ fs)
{
    int i = blockIdx.x * blockDim.x + threadIdx.x;  // float4 idx, NB*1536 total
    if (i >= NB * 1536) return;
    int b = i / 1536;
    int j = (i % 1536) * 4;

    float4 v = make_float4(0.f, 0.f, 0.f, 0.f);
#pragma unroll
    for (int s = 0; s < QKV_SPLIT; s++) {
        float4 t = *(const float4*)&g_part[(size_t)s * NB * 6144 +
                                           (size_t)b * 6144 + j];
        v.x += t.x; v.y += t.y; v.z += t.z; v.w += t.w;
    }

    if (j < 5120) {
        int p0 = (j & 127) >> 1;
        int p1 = ((j + 2) & 127) >> 1;
        float c0 = fc[p0], s0 = fs[p0];
        float c1 = fc[p1], s1 = fs[p1];
        float4 o;
        o.x = v.x * c0 - v.y * s0;
        o.y = v.x * s0 + v.y * c0;
        o.z = v.z * c1 - v.w * s1;
        o.w = v.z * s1 + v.w * c1;
        if (j < 4096)
            *(float4*)&g_q[b * DIM + j] = o;
        else
            *(float4*)&g_k[b * 1024 + j - 4096] = o;
    } else {
        *(float4*)&g_v[b * 1024 + j - 5120] = v;
    }
}

// ------------------------- cp.async helpers ---------------------------------
__device__ __forceinline__ void cp16(unsigned dst, const float* src)
{
    asm volatile("cp.async.cg.shared.global [%0], [%1], 16;"
                 :: "r"(dst), "l"(src) : "memory");
}
#define CP_COMMIT() asm volatile("cp.async.commit_group;" ::: "memory")
#define CP_WAIT1()  asm volatile("cp.async.wait_group 1;" ::: "memory")
#define CP_WAIT0()  asm volatile("cp.async.wait_group 0;" ::: "memory")

// ------------------------- flash-decode attention ---------------------------
// One block per (b, kv_head, chunk=512). 128 threads = 4 warps.
// Q in registers; K/V staged via cp.async (double-buffered); per-warp
// phase-3 partials go straight to g_pout.
__global__ __launch_bounds__(128, 5) void attn_kernel(
    const float* __restrict__ cache_k, const float* __restrict__ cache_v,
    const int* __restrict__ sp)
{
    int blk = blockIdx.x;                 // c + 4*(h + 8*b)
    int c = blk & 3;
    int h = (blk >> 2) & 7;
    int b = blk >> 5;

    int tid = threadIdx.x;
    int w = tid >> 5, lane = tid & 31;
    int rowgrp = lane >> 3;               // 0..3
    int e      = lane & 7;                // dim-eighth

    int start_pos = *sp;
    int t_total = start_pos + 1;

    __shared__ float ts[2][32][TSS];      // staged K/V tiles, 33.8KB
    __shared__ float sc[CHUNK][4];        // scores -> probs, 8KB

    unsigned ts_smem = (unsigned)__cvta_generic_to_shared(&ts[0][0][0]);

    const float scale = 0.08838834764831845f;  // 1/sqrt(128)

    // Q in registers: qreg[rep][qq] over dims quads e+8*qq
    float4 qreg[4][4];
#pragma unroll
    for (int r = 0; r < 4; r++)
#pragma unroll
        for (int qq = 0; qq < 4; qq++) {
            float4 v = *(const float4*)&g_q[(size_t)b * DIM + (h * NREP + r) * HD +
                                            (e + 8 * qq) * 4];
            qreg[r][qq] = make_float4(v.x * scale, v.y * scale,
                                      v.z * scale, v.w * scale);
        }

    int tbase = c * CHUNK;
    const float* knew = &g_k[(size_t)b * 1024 + h * HD];
    const float* vnew = &g_v[(size_t)b * 1024 + h * HD];

    // ======================= phase 1: scores (K stream) =====================
    {
#pragma unroll
        for (int jj = 0; jj < 8; jj++) {
            int row = w + 4 * jj;
            int tpos = tbase + row;
            int tp = tpos < start_pos ? tpos : start_pos;
            const float* src = (tp == start_pos)
                ? knew : &cache_k[(((size_t)b * MAXSEQ + tp) * NKV + h) * HD];
            cp16(ts_smem + (unsigned)(row * TSS + lane * 4) * 4, src + lane * 4);
        }
        CP_COMMIT();
    }

    int buf = 0;
    for (int tile = 0; tile < NTILE; tile++) {
        if (tile < NTILE - 1) {
            int trow0 = tbase + (tile + 1) * 32;
            unsigned bofs = ts_smem + (unsigned)((buf ^ 1) * 32 * TSS) * 4;
#pragma unroll
            for (int jj = 0; jj < 8; jj++) {
                int row = w + 4 * jj;
                int tpos = trow0 + row;
                int tp = tpos < start_pos ? tpos : start_pos;
                const float* src = (tp == start_pos)
                    ? knew : &cache_k[(((size_t)b * MAXSEQ + tp) * NKV + h) * HD];
                cp16(bofs + (unsigned)(row * TSS + lane * 4) * 4, src + lane * 4);
            }
            CP_COMMIT();
            CP_WAIT1();
        } else {
            CP_WAIT0();
        }
        __syncthreads();

#pragma unroll
        for (int rr = 0; rr < 2; rr++) {
            int row = w * 8 + rowgrp + 4 * rr;
            float s0 = 0.f, s1 = 0.f, s2 = 0.f, s3 = 0.f;
#pragma unroll
            for (int qq = 0; qq < 4; qq++) {
                float4 k4 = *(const float4*)&ts[buf][row][(e + 8 * qq) * 4];
                s0 += k4.x * qreg[0][qq].x + k4.y * qreg[0][qq].y +
                      k4.z * qreg[0][qq].z + k4.w * qreg[0][qq].w;
                s1 += k4.x * qreg[1][qq].x + k4.y * qreg[1][qq].y +
                      k4.z * qreg[1][qq].z + k4.w * qreg[1][qq].w;
                s2 += k4.x * qreg[2][qq].x + k4.y * qreg[2][qq].y +
                      k4.z * qreg[2][qq].z + k4.w * qreg[2][qq].w;
                s3 += k4.x * qreg[3][qq].x + k4.y * qreg[3][qq].y +
                      k4.z * qreg[3][qq].z + k4.w * qreg[3][qq].w;
            }
#pragma unroll
            for (int off = 1; off < 8; off <<= 1) {
                s0 += __shfl_xor_sync(0xffffffffu, s0, off);
                s1 += __shfl_xor_sync(0xffffffffu, s1, off);
                s2 += __shfl_xor_sync(0xffffffffu, s2, off);
                s3 += __shfl_xor_sync(0xffffffffu, s3, off);
            }
            if (e == 0) {
                int tl = tile * 32 + row;
                bool valid = (tbase + tl) < t_total;
                *(float4*)&sc[tl][0] = valid
                    ? make_float4(s0, s1, s2, s3)
                    : make_float4(-INFINITY, -INFINITY, -INFINITY, -INFINITY);
            }
        }
        __syncthreads();
        buf ^= 1;
    }

    // ======================= phase 2: partial softmax =======================
    {
        int r = w;
        float sv[NTILE];
        float m = -INFINITY;
#pragma unroll
        for (int i = 0; i < NTILE; i++) {
            sv[i] = sc[lane + 32 * i][r];
            m = fmaxf(m, sv[i]);
        }
#pragma unroll
        for (int off = 16; off > 0; off >>= 1)
            m = fmaxf(m, __shfl_xor_sync(0xffffffffu, m, off));
        float lsum = 0.f;
#pragma unroll
        for (int i = 0; i < NTILE; i++) {
            float p = (m == -INFINITY) ? 0.f : __expf(sv[i] - m);
            sc[lane + 32 * i][r] = p;
            lsum += p;
        }
#pragma unroll
        for (int off = 16; off > 0; off >>= 1)
            lsum += __shfl_xor_sync(0xffffffffu, lsum, off);
        if (lane == 0) {
            size_t mlidx = ((((size_t)b * NKV + h) * NREP + r) * NCHUNK + c) * 2;
            g_ml[mlidx]     = m;
            g_ml[mlidx + 1] = lsum;
        }
    }
    __syncthreads();

    // ======================= phase 3: P @ V (V stream) ======================
    float4 acc0 = make_float4(0.f, 0.f, 0.f, 0.f);
    float4 acc1 = acc0, acc2 = acc0, acc3 = acc0;

    {
#pragma unroll
        for (int jj = 0; jj < 8; jj++) {
            int row = w + 4 * jj;
            int tpos = tbase + row;
            int tp = tpos < start_pos ? tpos : start_pos;
            const float* src = (tp == start_pos)
                ? vnew : &cache_v[(((size_t)b * MAXSEQ + tp) * NKV + h) * HD];
            cp16(ts_smem + (unsigned)(row * TSS + lane * 4) * 4, src + lane * 4);
        }
        CP_COMMIT();
    }

    buf = 0;
    for (int tile = 0; tile < NTILE; tile++) {
        if (tile < NTILE - 1) {
            int trow0 = tbase + (tile + 1) * 32;
            unsigned bofs = ts_smem + (unsigned)((buf ^ 1) * 32 * TSS) * 4;
#pragma unroll
            for (int jj = 0; jj < 8; jj++) {
                int row = w + 4 * jj;
                int tpos = trow0 + row;
                int tp = tpos < start_pos ? tpos : start_pos;
                const float* src = (tp == start_pos)
                    ? vnew : &cache_v[(((size_t)b * MAXSEQ + tp) * NKV + h) * HD];
                cp16(bofs + (unsigned)(row * TSS + lane * 4) * 4, src + lane * 4);
            }
            CP_COMMIT();
            CP_WAIT1();
        } else {
            CP_WAIT0();
        }
        __syncthreads();

#pragma unroll
        for (int rr = 0; rr < 8; rr++) {
            int row = w * 8 + rr;
            float4 p  = *(const float4*)&sc[tile * 32 + row][0];
            float4 v4 = *(const float4*)&ts[buf][row][lane * 4];
            acc0.x += p.x * v4.x; acc0.y += p.x * v4.y; acc0.z += p.x * v4.z; acc0.w += p.x * v4.w;
            acc1.x += p.y * v4.x; acc1.y += p.y * v4.y; acc1.z += p.y * v4.z; acc1.w += p.y * v4.w;
            acc2.x += p.z * v4.x; acc2.y += p.z * v4.y; acc2.z += p.z * v4.z; acc2.w += p.z * v4.w;
            acc3.x += p.w * v4.x; acc3.y += p.w * v4.y; acc3.z += p.w * v4.z; acc3.w += p.w * v4.w;
        }
        __syncthreads();
        buf ^= 1;
    }

    // per-warp partials: [b][h][c][warp][rep][HD]
    size_t obase = ((((size_t)(b * NKV + h) * NCHUNK + c) * 4 + w) * NREP) * HD;
    *(float4*)&g_pout[obase + 0 * HD + lane * 4] = acc0;
    *(float4*)&g_pout[obase + 1 * HD + lane * 4] = acc1;
    *(float4*)&g_pout[obase + 2 * HD + lane * 4] = acc2;
    *(float4*)&g_pout[obase + 3 * HD + lane * 4] = acc3;
}

// ------------------------- combine partial softmax --------------------------
// One block per (b, h); 128 threads = 4 reps x 32 lanes; lane owns d-quad.
__global__ __launch_bounds__(128) void combine_kernel()
{
    int blk = blockIdx.x;                 // h + 8*b
    int h = blk & 7;
    int b = blk >> 3;
    int r = threadIdx.x >> 5;
    int lane = threadIdx.x & 31;

    size_t mlb = (((size_t)b * NKV + h) * NREP + r) * NCHUNK;

    float mm[NCHUNK], ll[NCHUNK];
    float mg = -INFINITY;
#pragma unroll
    for (int c = 0; c < NCHUNK; c++) {
        mm[c] = g_ml[(mlb + c) * 2];
        ll[c] = g_ml[(mlb + c) * 2 + 1];
        if (ll[c] > 0.f) mg = fmaxf(mg, mm[c]);
    }
    float L = 0.f;
    float4 o = make_float4(0.f, 0.f, 0.f, 0.f);
#pragma unroll
    for (int c = 0; c < NCHUNK; c++) {
        if (ll[c] > 0.f) {
            float f = __expf(mm[c] - mg);
            L += ll[c] * f;
            size_t pb = ((((size_t)(b * NKV + h) * NCHUNK + c) * 4) * NREP + r) * HD
                        + lane * 4;
            float4 s0 = *(const float4*)&g_pout[pb];
            float4 s1 = *(const float4*)&g_pout[pb + NREP * HD];
            float4 s2 = *(const float4*)&g_pout[pb + 2 * NREP * HD];
            float4 s3 = *(const float4*)&g_pout[pb + 3 * NREP * HD];
            float4 s = make_float4(s0.x + s1.x + s2.x + s3.x,
                                   s0.y + s1.y + s2.y + s3.y,
                                   s0.z + s1.z + s2.z + s3.z,
                                   s0.w + s1.w + s2.w + s3.w);
            o.x += f * s.x; o.y += f * s.y; o.z += f * s.z; o.w += f * s.w;
        }
    }
    float inv = 1.f / L;
    *(float4*)&g_attn[(size_t)b * DIM + (h * NREP + r) * HD + lane * 4] =
        make_float4(o.x * inv, o.y * inv, o.z * inv, o.w * inv);
}

// ------------------------- O-proj split-K reduce ----------------------------
__global__ void o_finish(float* __restrict__ out)
{
    int i = blockIdx.x * blockDim.x + threadIdx.x;  // 32768 float4 elems
    if (i >= NB * DIM / 4) return;
    float4 s = make_float4(0.f, 0.f, 0.f, 0.f);
#pragma unroll
    for (int p = 0; p < O_SPLIT; p++) {
        float4 v = *((const float4*)&g_part[(size_t)p * NB * DIM] + i);
        s.x += v.x; s.y += v.y; s.z += v.z; s.w += v.w;
    }
    ((float4*)out)[i] = s;
}

// ------------------------- launcher -----------------------------------------
extern "C" void kernel_launch(void* const* d_in, const int* in_sizes, int n_in,
                              void* d_out, int out_size)
{
    const float* x  = (const float*)d_in[0];
    const float* fc = (const float*)d_in[1];
    const float* fs = (const float*)d_in[2];
    const float* wq = (const float*)d_in[3];
    const float* wk = (const float*)d_in[4];
    const float* wv = (const float*)d_in[5];
    const float* wo = (const float*)d_in[6];
    const float* ck = (const float*)d_in[7];
    const float* cv = (const float*)d_in[8];
    const int*   sp = (const int*)d_in[9];
    float* out = (float*)d_out;

    // QKV projection: 48 n-slabs x split 8 = 384 blocks, klen 512
    proj_mma<<<48 * QKV_SPLIT, 128>>>(x, wq, wk, wv, 48, 4096, 5120,
                                      4096 / QKV_SPLIT, 6144);
    qkv_finish<<<192, 256>>>(fc, fs);
    // attention partials: 32*8*4 = 1024 blocks
    attn_kernel<<<1024, 128>>>(ck, cv, sp);
    combine_kernel<<<256, 128>>>();
    // O projection: 32 n-slabs x split 8 = 256 blocks, klen 512
    proj_mma<<<32 * O_SPLIT, 128>>>(nullptr, wo, wo, wo, 32, 4096, 8192,
                                    4096 / O_SPLIT, 4096);
    o_finish<<<128, 256>>>(out);
}

// round 15
// speedup vs baseline: 1.1611x; 1.1611x over previous
#include <cuda_runtime.h>
#include <cuda_bf16.h>
#include <cstdint>
#include <math.h>

#define NB 32
#define DIM 4096
#define NKV 8
#define NREP 4
#define HD 128
#define MAXSEQ 2048
#define NCHUNK 8
#define CHUNK 256
#define NTILE 8
#define QKV_SPLIT 16
#define O_SPLIT 16
#define TSS 132   // tile row stride (floats)

// ------------------------- device scratch (no allocs allowed) ---------------
__device__ float g_q[NB * DIM];                          // rope'd Q
__device__ float g_k[NB * NKV * HD];                     // rope'd new K row
__device__ float g_v[NB * NKV * HD];                     // new V row
__device__ float g_attn[NB * DIM];                       // attention output
__device__ float g_part[QKV_SPLIT * NB * 6144];          // split-K partials
__device__ float g_pout[NB * NKV * NCHUNK * 4 * NREP * HD];  // per-warp partials
__device__ float g_ml[NB * NKV * NREP * NCHUNK * 2];     // (m, l) per chunk

// ------------------------- bf16x3 MMA projection GEMM -----------------------
#define MMA_B16(acc, A0, A1, A2, A3, B0, B1)                                   \
    asm volatile(                                                              \
        "mma.sync.aligned.m16n8k16.row.col.f32.bf16.bf16.f32 "                 \
        "{%0,%1,%2,%3}, {%4,%5,%6,%7}, {%8,%9}, {%0,%1,%2,%3};"                \
        : "+f"(acc[0]), "+f"(acc[1]), "+f"(acc[2]), "+f"(acc[3])               \
        : "r"(A0), "r"(A1), "r"(A2), "r"(A3), "r"(B0), "r"(B1))

// packed split: one F2FP.PACK for hi pair, one for lo pair
__device__ __forceinline__ void bf16_split2(float2 v, unsigned& uh, unsigned& ul)
{
    __nv_bfloat162 hb = __floats2bfloat162_rn(v.x, v.y);
    float2 hf = __bfloat1622float2(hb);
    __nv_bfloat162 lb = __floats2bfloat162_rn(v.x - hf.x, v.y - hf.y);
    uh = *reinterpret_cast<unsigned*>(&hb);
    ul = *reinterpret_cast<unsigned*>(&lb);
}

__global__ __launch_bounds__(128) void proj_mma(
    const float* __restrict__ A,   // NB x 4096 (nullptr -> g_attn)
    const float* __restrict__ W0,
    const float* __restrict__ W1,
    const float* __restrict__ W2,
    int njb, int r1, int r2, int klen, int totalj)
{
    __shared__ unsigned sB[16 * 4 * 144];   // 36 KB
    __shared__ unsigned sAh[2 * 4 * 132];   // 4.2 KB
    __shared__ unsigned sAl[2 * 4 * 132];   // 4.2 KB

    const float* Ap = A ? A : g_attn;

    int jb    = blockIdx.x % njb;
    int split = blockIdx.x / njb;
    int j0    = jb * 128;

    const float* W;
    int jw;
    if (j0 < r1)      { W = W0; jw = j0; }
    else if (j0 < r2) { W = W1; jw = j0 - r1; }
    else              { W = W2; jw = j0 - r2; }

    int tid = threadIdx.x;
    int w   = tid >> 5, l = tid & 31;

    float acc[2][4][4];
#pragma unroll
    for (int i = 0; i < 2; i++)
#pragma unroll
        for (int j = 0; j < 4; j++)
#pragma unroll
            for (int c = 0; c < 4; c++) acc[i][j][c] = 0.f;

    int k0 = split * klen;
    int ksw   = l >> 3;
    int prw   = (l >> 2) & 1;
    int lq    = l & 3;

    for (int kc = k0; kc < k0 + klen; kc += 64) {
        __syncthreads();
#pragma unroll 4
        for (int rr = 0; rr < 32; rr++) {
            int n = w * 32 + rr;
            float2 v = *(const float2*)(W + (size_t)(jw + n) * 4096 + kc + 2 * l);
            unsigned uh, ul;
            bf16_split2(v, uh, ul);
            int nt = n >> 3;
            int lanep = ((n & 7) << 2) + lq;
            *(uint2*)&sB[((nt * 4 + ksw) * 144) + lanep * 4 + prw * 2] =
                make_uint2(uh, ul);
        }
#pragma unroll
        for (int rr = 0; rr < 8; rr++) {
            int m = w * 8 + rr;
            float2 v = *(const float2*)(Ap + (size_t)m * 4096 + kc + 2 * l);
            unsigned uh, ul;
            bf16_split2(v, uh, ul);
            int mt = m >> 4;
            int lanep = ((m & 7) << 2) + lq;
            int anum  = ((m >> 3) & 1) | (prw << 1);
            int idx = (mt * 4 + ksw) * 132 + lanep * 4 + anum;
            sAh[idx] = uh;
            sAl[idx] = ul;
        }
        __syncthreads();

#pragma unroll
        for (int ks = 0; ks < 4; ks++) {
            uint4 ah0 = *(const uint4*)&sAh[(ks) * 132 + l * 4];
            uint4 al0 = *(const uint4*)&sAl[(ks) * 132 + l * 4];
            uint4 ah1 = *(const uint4*)&sAh[(4 + ks) * 132 + l * 4];
            uint4 al1 = *(const uint4*)&sAl[(4 + ks) * 132 + l * 4];
#pragma unroll
            for (int ntl = 0; ntl < 4; ntl++) {
                uint4 bb = *(const uint4*)&sB[((w * 4 + ntl) * 4 + ks) * 144 + l * 4];
                MMA_B16(acc[0][ntl], ah0.x, ah0.y, ah0.z, ah0.w, bb.x, bb.z);
                MMA_B16(acc[1][ntl], ah1.x, ah1.y, ah1.z, ah1.w, bb.x, bb.z);
                MMA_B16(acc[0][ntl], al0.x, al0.y, al0.z, al0.w, bb.x, bb.z);
                MMA_B16(acc[1][ntl], al1.x, al1.y, al1.z, al1.w, bb.x, bb.z);
                MMA_B16(acc[0][ntl], ah0.x, ah0.y, ah0.z, ah0.w, bb.y, bb.w);
                MMA_B16(acc[1][ntl], ah1.x, ah1.y, ah1.z, ah1.w, bb.y, bb.w);
            }
        }
    }

    size_t pbase = (size_t)split * NB * totalj;
#pragma unroll
    for (int mt = 0; mt < 2; mt++)
#pragma unroll
        for (int ntl = 0; ntl < 4; ntl++) {
            int m = mt * 16 + (l >> 2);
            int j = j0 + ((w * 4 + ntl) << 3) + (lq << 1);
            *(float2*)&g_part[pbase + (size_t)m * totalj + j] =
                make_float2(acc[mt][ntl][0], acc[mt][ntl][1]);
            *(float2*)&g_part[pbase + (size_t)(m + 8) * totalj + j] =
                make_float2(acc[mt][ntl][2], acc[mt][ntl][3]);
        }
}

// ------------------------- split-K reduce + RoPE (float4) -------------------
__global__ void qkv_finish(const float* __restrict__ fc, const float* __restrict__ fs)
{
    int i = blockIdx.x * blockDim.x + threadIdx.x;  // float4 idx, NB*1536 total
    if (i >= NB * 1536) return;
    int b = i / 1536;
    int j = (i % 1536) * 4;

    float4 v = make_float4(0.f, 0.f, 0.f, 0.f);
#pragma unroll
    for (int s = 0; s < QKV_SPLIT; s++) {
        float4 t = *(const float4*)&g_part[(size_t)s * NB * 6144 +
                                           (size_t)b * 6144 + j];
        v.x += t.x; v.y += t.y; v.z += t.z; v.w += t.w;
    }

    if (j < 5120) {
        int p0 = (j & 127) >> 1;
        int p1 = ((j + 2) & 127) >> 1;
        float c0 = fc[p0], s0 = fs[p0];
        float c1 = fc[p1], s1 = fs[p1];
        float4 o;
        o.x = v.x * c0 - v.y * s0;
        o.y = v.x * s0 + v.y * c0;
        o.z = v.z * c1 - v.w * s1;
        o.w = v.z * s1 + v.w * c1;
        if (j < 4096)
            *(float4*)&g_q[b * DIM + j] = o;
        else
            *(float4*)&g_k[b * 1024 + j - 4096] = o;
    } else {
        *(float4*)&g_v[b * 1024 + j - 5120] = v;
    }
}

// ------------------------- cp.async helpers ---------------------------------
__device__ __forceinline__ void cp16(unsigned dst, const float* src)
{
    asm volatile("cp.async.cg.shared.global [%0], [%1], 16;"
                 :: "r"(dst), "l"(src) : "memory");
}
#define CP_COMMIT() asm volatile("cp.async.commit_group;" ::: "memory")
#define CP_WAIT1()  asm volatile("cp.async.wait_group 1;" ::: "memory")
#define CP_WAIT0()  asm volatile("cp.async.wait_group 0;" ::: "memory")

// ------------------------- flash-decode attention ---------------------------
// One block per (b, kv_head, chunk=256). 128 threads = 4 warps.
// Q in registers; K/V staged via cp.async (double-buffered); per-warp
// phase-3 partials go straight to g_pout.
__global__ __launch_bounds__(128, 5) void attn_kernel(
    const float* __restrict__ cache_k, const float* __restrict__ cache_v,
    const int* __restrict__ sp)
{
    int blk = blockIdx.x;                 // c + 8*(h + 8*b)
    int c = blk & 7;
    int h = (blk >> 3) & 7;
    int b = blk >> 6;

    int tid = threadIdx.x;
    int w = tid >> 5, lane = tid & 31;
    int rowgrp = lane >> 3;               // 0..3
    int e      = lane & 7;                // dim-eighth

    int start_pos = *sp;
    int t_total = start_pos + 1;

    __shared__ float ts[2][32][TSS];      // staged K/V tiles, 33.8KB
    __shared__ float sc[CHUNK][4];        // scores -> probs, 4KB

    unsigned ts_smem = (unsigned)__cvta_generic_to_shared(&ts[0][0][0]);

    const float scale = 0.08838834764831845f;  // 1/sqrt(128)

    // Q in registers: qreg[rep][qq] over dims quads e+8*qq
    float4 qreg[4][4];
#pragma unroll
    for (int r = 0; r < 4; r++)
#pragma unroll
        for (int qq = 0; qq < 4; qq++) {
            float4 v = *(const float4*)&g_q[(size_t)b * DIM + (h * NREP + r) * HD +
                                            (e + 8 * qq) * 4];
            qreg[r][qq] = make_float4(v.x * scale, v.y * scale,
                                      v.z * scale, v.w * scale);
        }

    int tbase = c * CHUNK;
    const float* knew = &g_k[(size_t)b * 1024 + h * HD];
    const float* vnew = &g_v[(size_t)b * 1024 + h * HD];

    // ======================= phase 1: scores (K stream) =====================
    {
#pragma unroll
        for (int jj = 0; jj < 8; jj++) {
            int row = w + 4 * jj;
            int tpos = tbase + row;
            int tp = tpos < start_pos ? tpos : start_pos;
            const float* src = (tp == start_pos)
                ? knew : &cache_k[(((size_t)b * MAXSEQ + tp) * NKV + h) * HD];
            cp16(ts_smem + (unsigned)(row * TSS + lane * 4) * 4, src + lane * 4);
        }
        CP_COMMIT();
    }

    int buf = 0;
    for (int tile = 0; tile < NTILE; tile++) {
        if (tile < NTILE - 1) {
            int trow0 = tbase + (tile + 1) * 32;
            unsigned bofs = ts_smem + (unsigned)((buf ^ 1) * 32 * TSS) * 4;
#pragma unroll
            for (int jj = 0; jj < 8; jj++) {
                int row = w + 4 * jj;
                int tpos = trow0 + row;
                int tp = tpos < start_pos ? tpos : start_pos;
                const float* src = (tp == start_pos)
                    ? knew : &cache_k[(((size_t)b * MAXSEQ + tp) * NKV + h) * HD];
                cp16(bofs + (unsigned)(row * TSS + lane * 4) * 4, src + lane * 4);
            }
            CP_COMMIT();
            CP_WAIT1();
        } else {
            CP_WAIT0();
        }
        __syncthreads();

#pragma unroll
        for (int rr = 0; rr < 2; rr++) {
            int row = w * 8 + rowgrp + 4 * rr;
            float s0 = 0.f, s1 = 0.f, s2 = 0.f, s3 = 0.f;
#pragma unroll
            for (int qq = 0; qq < 4; qq++) {
                float4 k4 = *(const float4*)&ts[buf][row][(e + 8 * qq) * 4];
                s0 += k4.x * qreg[0][qq].x + k4.y * qreg[0][qq].y +
                      k4.z * qreg[0][qq].z + k4.w * qreg[0][qq].w;
                s1 += k4.x * qreg[1][qq].x + k4.y * qreg[1][qq].y +
                      k4.z * qreg[1][qq].z + k4.w * qreg[1][qq].w;
                s2 += k4.x * qreg[2][qq].x + k4.y * qreg[2][qq].y +
                      k4.z * qreg[2][qq].z + k4.w * qreg[2][qq].w;
                s3 += k4.x * qreg[3][qq].x + k4.y * qreg[3][qq].y +
                      k4.z * qreg[3][qq].z + k4.w * qreg[3][qq].w;
            }
#pragma unroll
            for (int off = 1; off < 8; off <<= 1) {
                s0 += __shfl_xor_sync(0xffffffffu, s0, off);
                s1 += __shfl_xor_sync(0xffffffffu, s1, off);
                s2 += __shfl_xor_sync(0xffffffffu, s2, off);
                s3 += __shfl_xor_sync(0xffffffffu, s3, off);
            }
            if (e == 0) {
                int tl = tile * 32 + row;
                bool valid = (tbase + tl) < t_total;
                *(float4*)&sc[tl][0] = valid
                    ? make_float4(s0, s1, s2, s3)
                    : make_float4(-INFINITY, -INFINITY, -INFINITY, -INFINITY);
            }
        }
        __syncthreads();
        buf ^= 1;
    }

    // ======================= phase 2: partial softmax =======================
    {
        int r = w;
        float sv[NTILE];
        float m = -INFINITY;
#pragma unroll
        for (int i = 0; i < NTILE; i++) {
            sv[i] = sc[lane + 32 * i][r];
            m = fmaxf(m, sv[i]);
        }
#pragma unroll
        for (int off = 16; off > 0; off >>= 1)
            m = fmaxf(m, __shfl_xor_sync(0xffffffffu, m, off));
        float lsum = 0.f;
#pragma unroll
        for (int i = 0; i < NTILE; i++) {
            float p = (m == -INFINITY) ? 0.f : __expf(sv[i] - m);
            sc[lane + 32 * i][r] = p;
            lsum += p;
        }
#pragma unroll
        for (int off = 16; off > 0; off >>= 1)
            lsum += __shfl_xor_sync(0xffffffffu, lsum, off);
        if (lane == 0) {
            size_t mlidx = ((((size_t)b * NKV + h) * NREP + r) * NCHUNK + c) * 2;
            g_ml[mlidx]     = m;
            g_ml[mlidx + 1] = lsum;
        }
    }
    __syncthreads();

    // ======================= phase 3: P @ V (V stream) ======================
    float4 acc0 = make_float4(0.f, 0.f, 0.f, 0.f);
    float4 acc1 = acc0, acc2 = acc0, acc3 = acc0;

    {
#pragma unroll
        for (int jj = 0; jj < 8; jj++) {
            int row = w + 4 * jj;
            int tpos = tbase + row;
            int tp = tpos < start_pos ? tpos : start_pos;
            const float* src = (tp == start_pos)
                ? vnew : &cache_v[(((size_t)b * MAXSEQ + tp) * NKV + h) * HD];
            cp16(ts_smem + (unsigned)(row * TSS + lane * 4) * 4, src + lane * 4);
        }
        CP_COMMIT();
    }

    buf = 0;
    for (int tile = 0; tile < NTILE; tile++) {
        if (tile < NTILE - 1) {
            int trow0 = tbase + (tile + 1) * 32;
            unsigned bofs = ts_smem + (unsigned)((buf ^ 1) * 32 * TSS) * 4;
#pragma unroll
            for (int jj = 0; jj < 8; jj++) {
                int row = w + 4 * jj;
                int tpos = trow0 + row;
                int tp = tpos < start_pos ? tpos : start_pos;
                const float* src = (tp == start_pos)
                    ? vnew : &cache_v[(((size_t)b * MAXSEQ + tp) * NKV + h) * HD];
                cp16(bofs + (unsigned)(row * TSS + lane * 4) * 4, src + lane * 4);
            }
            CP_COMMIT();
            CP_WAIT1();
        } else {
            CP_WAIT0();
        }
        __syncthreads();

#pragma unroll
        for (int rr = 0; rr < 8; rr++) {
            int row = w * 8 + rr;
            float4 p  = *(const float4*)&sc[tile * 32 + row][0];
            float4 v4 = *(const float4*)&ts[buf][row][lane * 4];
            acc0.x += p.x * v4.x; acc0.y += p.x * v4.y; acc0.z += p.x * v4.z; acc0.w += p.x * v4.w;
            acc1.x += p.y * v4.x; acc1.y += p.y * v4.y; acc1.z += p.y * v4.z; acc1.w += p.y * v4.w;
            acc2.x += p.z * v4.x; acc2.y += p.z * v4.y; acc2.z += p.z * v4.z; acc2.w += p.z * v4.w;
            acc3.x += p.w * v4.x; acc3.y += p.w * v4.y; acc3.z += p.w * v4.z; acc3.w += p.w * v4.w;
        }
        __syncthreads();
        buf ^= 1;
    }

    // per-warp partials: [b][h][c][warp][rep][HD]
    size_t obase = ((((size_t)(b * NKV + h) * NCHUNK + c) * 4 + w) * NREP) * HD;
    *(float4*)&g_pout[obase + 0 * HD + lane * 4] = acc0;
    *(float4*)&g_pout[obase + 1 * HD + lane * 4] = acc1;
    *(float4*)&g_pout[obase + 2 * HD + lane * 4] = acc2;
    *(float4*)&g_pout[obase + 3 * HD + lane * 4] = acc3;
}

// ------------------------- combine partial softmax --------------------------
// One block per (b, h, rep); 128 threads = 4 warp-slots x 32 lanes.
// Each thread accumulates its warp-slot's weighted partial over all chunks
// (8 independent LDG.128), then smem-reduce across the 4 slots.
__global__ __launch_bounds__(128) void combine_kernel()
{
    int blk = blockIdx.x;                 // r + 4*(h + 8*b)
    int r = blk & 3;
    int h = (blk >> 2) & 7;
    int b = blk >> 5;

    int ws   = threadIdx.x >> 5;          // warp-slot 0..3
    int lane = threadIdx.x & 31;          // d-quad

    __shared__ float red[4][32][4];

    size_t mlb = (((size_t)b * NKV + h) * NREP + r) * NCHUNK;

    float mm[NCHUNK], ll[NCHUNK];
    float mg = -INFINITY;
#pragma unroll
    for (int c = 0; c < NCHUNK; c++) {
        mm[c] = g_ml[(mlb + c) * 2];
        ll[c] = g_ml[(mlb + c) * 2 + 1];
        if (ll[c] > 0.f) mg = fmaxf(mg, mm[c]);
    }
    float L = 0.f;
    float4 o = make_float4(0.f, 0.f, 0.f, 0.f);
#pragma unroll
    for (int c = 0; c < NCHUNK; c++) {
        if (ll[c] > 0.f) {
            float f = __expf(mm[c] - mg);
            L += ll[c] * f;
            size_t pb = ((((size_t)(b * NKV + h) * NCHUNK + c) * 4 + ws) * NREP + r)
                        * HD + lane * 4;
            float4 s = *(const float4*)&g_pout[pb];
            o.x += f * s.x; o.y += f * s.y; o.z += f * s.z; o.w += f * s.w;
        }
    }
    *(float4*)&red[ws][lane][0] = o;
    __syncthreads();
    if (ws == 0) {
        float4 t0 = *(const float4*)&red[0][lane][0];
        float4 t1 = *(const float4*)&red[1][lane][0];
        float4 t2 = *(const float4*)&red[2][lane][0];
        float4 t3 = *(const float4*)&red[3][lane][0];
        float inv = 1.f / L;
        *(float4*)&g_attn[(size_t)b * DIM + (h * NREP + r) * HD + lane * 4] =
            make_float4((t0.x + t1.x + t2.x + t3.x) * inv,
                        (t0.y + t1.y + t2.y + t3.y) * inv,
                        (t0.z + t1.z + t2.z + t3.z) * inv,
                        (t0.w + t1.w + t2.w + t3.w) * inv);
    }
}

// ------------------------- O-proj split-K reduce ----------------------------
__global__ void o_finish(float* __restrict__ out)
{
    int i = blockIdx.x * blockDim.x + threadIdx.x;  // 32768 float4 elems
    if (i >= NB * DIM / 4) return;
    float4 s = make_float4(0.f, 0.f, 0.f, 0.f);
#pragma unroll
    for (int p = 0; p < O_SPLIT; p++) {
        float4 v = *((const float4*)&g_part[(size_t)p * NB * DIM] + i);
        s.x += v.x; s.y += v.y; s.z += v.z; s.w += v.w;
    }
    ((float4*)out)[i] = s;
}

// ------------------------- launcher -----------------------------------------
extern "C" void kernel_launch(void* const* d_in, const int* in_sizes, int n_in,
                              void* d_out, int out_size)
{
    const float* x  = (const float*)d_in[0];
    const float* fc = (const float*)d_in[1];
    const float* fs = (const float*)d_in[2];
    const float* wq = (const float*)d_in[3];
    const float* wk = (const float*)d_in[4];
    const float* wv = (const float*)d_in[5];
    const float* wo = (const float*)d_in[6];
    const float* ck = (const float*)d_in[7];
    const float* cv = (const float*)d_in[8];
    const int*   sp = (const int*)d_in[9];
    float* out = (float*)d_out;

    // QKV projection: 48 n-slabs x split 16 = 768 blocks, klen 256
    proj_mma<<<48 * QKV_SPLIT, 128>>>(x, wq, wk, wv, 48, 4096, 5120,
                                      4096 / QKV_SPLIT, 6144);
    qkv_finish<<<192, 256>>>(fc, fs);
    // attention partials: 32*8*8 = 2048 blocks
    attn_kernel<<<2048, 128>>>(ck, cv, sp);
    // combine: 32*8*4 = 1024 blocks
    combine_kernel<<<1024, 128>>>();
    // O projection: 32 n-slabs x split 16 = 512 blocks, klen 256
    proj_mma<<<32 * O_SPLIT, 128>>>(nullptr, wo, wo, wo, 32, 4096, 8192,
                                    4096 / O_SPLIT, 4096);
    o_finish<<<128, 256>>>(out);
}